// round 1
// baseline (speedup 1.0000x reference)
#include <cuda_runtime.h>
#include <math.h>

// Problem dims
#define DM   512
#define LSEQ 256
#define BB   2
#define HH   8
#define DK   64
#define BH   16   // BB*HH
#define BL   512  // BB*LSEQ

#define NEG_BIG -1.0e30f
#define POS_BIG  1.0e30f

// ---------------- scratch (no allocations allowed) ----------------
__device__ float g_actq[BL * DM];
__device__ float g_actk[BL * DM];
__device__ float g_actv[BL * DM];
__device__ float g_Q[BH * LSEQ * DK];
__device__ float g_K[BH * LSEQ * DK];
__device__ float g_V[BH * LSEQ * DK];
__device__ float g_ctx[BL * DM];
__device__ float g_scores_fb[BH * LSEQ * LSEQ];

// ---------------- 64x64-tile fp32 GEMM: Y = X @ W^T (+ optional activation) --
// X: (512,512) row-major, W: (512,512) row-major (W[n][k]), Y: (512,512)
// If lam != nullptr: Y = log1p(relu(acc)) - lam[n]
__device__ __forceinline__ void gemm64(const float* __restrict__ X,
                                       const float* __restrict__ W,
                                       float* __restrict__ Y,
                                       const float* __restrict__ lam,
                                       int bm, int bn)
{
    __shared__ float As[16][68];
    __shared__ float Bs[16][68];

    const int tid = threadIdx.x;          // 256 threads
    const int tm  = tid >> 4;             // 0..15
    const int tn  = tid & 15;             // 0..15
    const int lk  = tid & 15;             // k-slot for loading
    const int lr  = tid >> 4;             // row-slot base

    float acc[4][4];
#pragma unroll
    for (int i = 0; i < 4; i++)
#pragma unroll
        for (int j = 0; j < 4; j++) acc[i][j] = 0.0f;

    for (int kt = 0; kt < DM; kt += 16) {
#pragma unroll
        for (int p = 0; p < 4; p++) {
            const int r = lr + p * 16;    // 0..63
            As[lk][r] = X[(bm * 64 + r) * DM + kt + lk];
            Bs[lk][r] = W[(bn * 64 + r) * DM + kt + lk];
        }
        __syncthreads();
#pragma unroll
        for (int kk = 0; kk < 16; kk++) {
            float a[4], b[4];
#pragma unroll
            for (int i = 0; i < 4; i++) a[i] = As[kk][tm * 4 + i];
#pragma unroll
            for (int j = 0; j < 4; j++) b[j] = Bs[kk][tn * 4 + j];
#pragma unroll
            for (int i = 0; i < 4; i++)
#pragma unroll
                for (int j = 0; j < 4; j++)
                    acc[i][j] = fmaf(a[i], b[j], acc[i][j]);
        }
        __syncthreads();
    }

#pragma unroll
    for (int i = 0; i < 4; i++) {
        const int m = bm * 64 + tm * 4 + i;
#pragma unroll
        for (int j = 0; j < 4; j++) {
            const int n = bn * 64 + tn * 4 + j;
            float v = acc[i][j];
            if (lam) v = log1pf(fmaxf(v, 0.0f)) - lam[n];
            Y[m * DM + n] = v;
        }
    }
}

// ---------------- K1: projections q/k/v = log1p(relu(x@W^T)) - lam ----------
__global__ __launch_bounds__(256) void k_proj(const float* __restrict__ X,
                                              const float* __restrict__ Wq,
                                              const float* __restrict__ Wk,
                                              const float* __restrict__ Wv,
                                              const float* __restrict__ lam)
{
    const float* W;
    float* Y;
    if (blockIdx.z == 0)      { W = Wq; Y = g_actq; }
    else if (blockIdx.z == 1) { W = Wk; Y = g_actk; }
    else                      { W = Wv; Y = g_actv; }
    gemm64(X, W, Y, lam, (int)blockIdx.y, (int)blockIdx.x);
}

// ---------------- K2: tropical linear per head --------------------------------
// out[bh, l, o] = max_i( act[b, l, h*64 + i] + Wt[o, i] )
__global__ __launch_bounds__(256) void k_trop(const float* __restrict__ Wqt,
                                              const float* __restrict__ Wkt,
                                              const float* __restrict__ Wvt)
{
    __shared__ float Wt[64][68];
    __shared__ float ar[4][64];

    const float* act; const float* W; float* out;
    if (blockIdx.z == 0)      { act = g_actq; W = Wqt; out = g_Q; }
    else if (blockIdx.z == 1) { act = g_actk; W = Wkt; out = g_K; }
    else                      { act = g_actv; W = Wvt; out = g_V; }

    const int tid = threadIdx.x;             // 256
    for (int idx = tid; idx < 64 * 64; idx += 256)
        Wt[idx >> 6][idx & 63] = W[idx];

    const int bh = blockIdx.y;
    const int b  = bh >> 3;
    const int h  = bh & 7;
    const int l0 = blockIdx.x * 4;
    const int ly = tid >> 6;                 // 0..3
    const int o  = tid & 63;                 // 0..63

    ar[ly][o] = act[((b * LSEQ) + l0 + ly) * DM + h * DK + o];
    __syncthreads();

    float m = NEG_BIG;
#pragma unroll
    for (int i = 0; i < 64; i++)
        m = fmaxf(m, ar[ly][i] + Wt[o][i]);

    out[(bh * LSEQ + l0 + ly) * DK + o] = m;
}

// ---------------- K3a: tropical metric scores ---------------------------------
// scores[bh,i,j] = min_d(q_i - k_j) - max_d(q_i - k_j)
__global__ __launch_bounds__(256) void k_scores(float* __restrict__ scores)
{
    __shared__ float4 Ks[128 * 16];          // 128 j-rows x 64 d = 32KB

    const int bh = blockIdx.y;
    const int it = blockIdx.x;               // i-tile of 32
    const int tid = threadIdx.x;
    const int ii = tid & 31;                 // warp lanes span i -> K broadcast
    const int jg = tid >> 5;                 // 0..7
    const int i  = it * 32 + ii;

    float4 q[16];
    const float4* Qp = (const float4*)(g_Q + (bh * LSEQ + i) * DK);
#pragma unroll
    for (int t = 0; t < 16; t++) q[t] = Qp[t];

    for (int c = 0; c < 2; c++) {
        const float4* Kp = (const float4*)(g_K + (bh * LSEQ + c * 128) * DK);
        for (int idx = tid; idx < 128 * 16; idx += 256) Ks[idx] = Kp[idx];
        __syncthreads();

#pragma unroll 2
        for (int jl = 0; jl < 16; jl++) {
            const int j = jg * 16 + jl;      // within chunk
            float mx = NEG_BIG, mn = POS_BIG;
#pragma unroll
            for (int t = 0; t < 16; t++) {
                const float4 kv = Ks[j * 16 + t];
                float d0 = q[t].x - kv.x;
                float d1 = q[t].y - kv.y;
                float d2 = q[t].z - kv.z;
                float d3 = q[t].w - kv.w;
                mx = fmaxf(mx, d0); mn = fminf(mn, d0);
                mx = fmaxf(mx, d1); mn = fminf(mn, d1);
                mx = fmaxf(mx, d2); mn = fminf(mn, d2);
                mx = fmaxf(mx, d3); mn = fminf(mn, d3);
            }
            scores[(bh * LSEQ + i) * LSEQ + c * 128 + j] = mn - mx;
        }
        __syncthreads();
    }
}

// ---------------- K3b: context = max-plus(scores, V), then expm1, head-merge --
__global__ __launch_bounds__(256) void k_ctx(const float* __restrict__ scores)
{
    __shared__ float4 Vs[128 * 16];          // 32KB
    __shared__ float  Ss[32][128];           // 16KB

    const int bh = blockIdx.y;
    const int it = blockIdx.x;               // i-tile of 32
    const int b  = bh >> 3;
    const int h  = bh & 7;
    const int tid = threadIdx.x;
    const int ii = tid >> 3;                 // 0..31
    const int dg = tid & 7;                  // 0..7 (8 d's each)

    float acc[8];
#pragma unroll
    for (int x = 0; x < 8; x++) acc[x] = NEG_BIG;

    for (int c = 0; c < 2; c++) {
        const float4* Vp = (const float4*)(g_V + (bh * LSEQ + c * 128) * DK);
        for (int idx = tid; idx < 128 * 16; idx += 256) Vs[idx] = Vp[idx];
        for (int idx = tid; idx < 32 * 128; idx += 256) {
            const int r = idx >> 7, col = idx & 127;
            Ss[r][col] = scores[(bh * LSEQ + it * 32 + r) * LSEQ + c * 128 + col];
        }
        __syncthreads();

#pragma unroll 4
        for (int j = 0; j < 128; j++) {
            const float s = Ss[ii][j];
            const float4 v0 = Vs[j * 16 + dg * 2];
            const float4 v1 = Vs[j * 16 + dg * 2 + 1];
            acc[0] = fmaxf(acc[0], s + v0.x);
            acc[1] = fmaxf(acc[1], s + v0.y);
            acc[2] = fmaxf(acc[2], s + v0.z);
            acc[3] = fmaxf(acc[3], s + v0.w);
            acc[4] = fmaxf(acc[4], s + v1.x);
            acc[5] = fmaxf(acc[5], s + v1.y);
            acc[6] = fmaxf(acc[6], s + v1.z);
            acc[7] = fmaxf(acc[7], s + v1.w);
        }
        __syncthreads();
    }

    const int l = it * 32 + ii;
    float* dst = g_ctx + (b * LSEQ + l) * DM + h * DK + dg * 8;
#pragma unroll
    for (int x = 0; x < 8; x++) dst[x] = expm1f(acc[x]);
}

// ---------------- K4: output = expm1(context) @ Wo^T --------------------------
__global__ __launch_bounds__(256) void k_out(const float* __restrict__ Wo,
                                             float* __restrict__ out)
{
    gemm64(g_ctx, Wo, out, nullptr, (int)blockIdx.y, (int)blockIdx.x);
}

// ---------------- launch ------------------------------------------------------
extern "C" void kernel_launch(void* const* d_in, const int* in_sizes, int n_in,
                              void* d_out, int out_size)
{
    const float* x   = (const float*)d_in[0];
    const float* Wq  = (const float*)d_in[1];
    const float* Wk  = (const float*)d_in[2];
    const float* Wv  = (const float*)d_in[3];
    const float* Wo  = (const float*)d_in[4];
    const float* lam = (const float*)d_in[5];
    const float* Wqt = (const float*)d_in[6];
    const float* Wkt = (const float*)d_in[7];
    const float* Wvt = (const float*)d_in[8];
    float* out = (float*)d_out;

    // Reference returns (output, attn_scores): output = 2*256*512 = 262144,
    // attn_scores = 16*256*256 = 1048576. If d_out holds both (flattened in
    // tuple order), write scores directly into it; otherwise use scratch.
    float* scores;
    cudaError_t dummy; (void)dummy;
    if (out_size >= (BL * DM + BH * LSEQ * LSEQ)) {
        scores = out + BL * DM;
    } else {
        // resolve device-global address at compile time via a tiny kernel-free path:
        // we can't call cudaGetSymbolAddress during capture safely on all stacks,
        // so launch-side kernels reference g_scores_fb directly; pass nullptr tag.
        scores = nullptr;
    }

    // projections
    k_proj<<<dim3(8, 8, 3), 256>>>(x, Wq, Wk, Wv, lam);
    // tropical linears
    k_trop<<<dim3(64, 16, 3), 256>>>(Wqt, Wkt, Wvt);

    if (scores) {
        k_scores<<<dim3(8, 16), 256>>>(scores);
        k_ctx<<<dim3(8, 16), 256>>>(scores);
    } else {
        // fallback path: scores kept in device scratch
        // (small shim kernels avoid host-side symbol lookup)
        // reuse same kernels by passing the scratch address obtained on device
        // via a launch that forwards g_scores_fb.
        // Simplest: dedicated wrappers.
        extern __global__ void k_scores_fb_wrap();
        // (not used; see wrappers below)
    }

    k_out<<<dim3(8, 8), 256>>>(Wo, out);
}

// Fallback wrappers (only used if out_size doesn't include scores; defined to
// keep the fallback graph-capturable without host symbol lookups).
__global__ __launch_bounds__(256) void k_scores_fb_kernel()
{
    // not reachable in the expected configuration
}

// round 2
// speedup vs baseline: 1.8380x; 1.8380x over previous
#include <cuda_runtime.h>
#include <math.h>

#define DM   512
#define LSEQ 256
#define BB   2
#define HH   8
#define DK   64
#define BH   16
#define BL   512
#define NEG_BIG -1.0e30f
#define POS_BIG  1.0e30f

typedef unsigned long long ull;

// ---------------- scratch (device globals; no allocations allowed) -----------
__device__ float g_pp[3 * 8 * BL * DM];   // projection split-K partials (25.2MB)
__device__ float g_op[8 * BL * DM];       // output GEMM split-K partials (8.4MB)
__device__ float g_Q[BH * LSEQ * DK];
__device__ float g_K[BH * LSEQ * DK];
__device__ float g_V[BH * LSEQ * DK];
__device__ float g_ctx[BL * DM];

// ---------------- packed f32x2 helpers ---------------------------------------
__device__ __forceinline__ ull pk2(float lo, float hi) {
    ull r;
    asm("mov.b64 %0, {%1, %2};" : "=l"(r) : "f"(lo), "f"(hi));
    return r;
}
__device__ __forceinline__ void upk2(ull v, float& lo, float& hi) {
    asm("mov.b64 {%0, %1}, %2;" : "=f"(lo), "=f"(hi) : "l"(v));
}
__device__ __forceinline__ void fma2(ull& acc, ull a, ull b) {
    asm("fma.rn.f32x2 %0, %1, %2, %0;" : "+l"(acc) : "l"(a), "l"(b));
}

// ---------------- split-K GEMM: P[zk] = X[:, zk*64:(zk+1)*64] @ W_chunk^T ----
// 128x128 tile, 256 threads, 8x8 per thread, packed f32x2 FFMA.
// mode 0: proj (3 gemms, X = x input, P = g_pp), grid (4,4,24)
// mode 1: out  (1 gemm,  X = g_ctx,  P = g_op),  grid (4,4,8)
__global__ __launch_bounds__(256, 2) void k_gemm(const float* __restrict__ Xin,
                                                 const float* __restrict__ W0,
                                                 const float* __restrict__ W1,
                                                 const float* __restrict__ W2,
                                                 int mode)
{
    __shared__ float As[16][132];
    __shared__ float Bs[16][132];

    const int gemm = blockIdx.z >> 3;
    const int zk   = blockIdx.z & 7;
    const float* X = mode ? (const float*)g_ctx : Xin;
    const float* W = (gemm == 0) ? W0 : ((gemm == 1) ? W1 : W2);
    float* P = (mode ? g_op : g_pp) + (gemm * 8 + zk) * (BL * DM);

    const int bm = blockIdx.y, bn = blockIdx.x;
    const int tid = threadIdx.x;
    const int tm = tid >> 4;          // 0..15
    const int tn = tid & 15;          // 0..15
    const int ml = tid & 127;         // load row
    const int kh = tid >> 7;          // 0..1

    ull acc[8][4];
#pragma unroll
    for (int i = 0; i < 8; i++)
#pragma unroll
        for (int j = 0; j < 4; j++) acc[i][j] = 0ULL;

    const int k0 = zk * 64;
    for (int kc = 0; kc < 64; kc += 16) {
#pragma unroll
        for (int p = 0; p < 2; p++) {
            const int kq = (kh * 2 + p) * 4;
            const float4 xa = *(const float4*)&X[(bm * 128 + ml) * DM + k0 + kc + kq];
            As[kq + 0][ml] = xa.x; As[kq + 1][ml] = xa.y;
            As[kq + 2][ml] = xa.z; As[kq + 3][ml] = xa.w;
            const float4 wb = *(const float4*)&W[(bn * 128 + ml) * DM + k0 + kc + kq];
            Bs[kq + 0][ml] = wb.x; Bs[kq + 1][ml] = wb.y;
            Bs[kq + 2][ml] = wb.z; Bs[kq + 3][ml] = wb.w;
        }
        __syncthreads();

#pragma unroll
        for (int kk = 0; kk < 16; kk++) {
            const float4 a0 = *(const float4*)&As[kk][tm * 8];
            const float4 a1 = *(const float4*)&As[kk][tm * 8 + 4];
            const float4 b0 = *(const float4*)&Bs[kk][tn * 8];
            const float4 b1 = *(const float4*)&Bs[kk][tn * 8 + 4];
            ull bp[4];
            bp[0] = pk2(b0.x, b0.y); bp[1] = pk2(b0.z, b0.w);
            bp[2] = pk2(b1.x, b1.y); bp[3] = pk2(b1.z, b1.w);
            float av[8] = {a0.x, a0.y, a0.z, a0.w, a1.x, a1.y, a1.z, a1.w};
#pragma unroll
            for (int i = 0; i < 8; i++) {
                const ull ad = pk2(av[i], av[i]);
#pragma unroll
                for (int j = 0; j < 4; j++) fma2(acc[i][j], ad, bp[j]);
            }
        }
        __syncthreads();
    }

#pragma unroll
    for (int i = 0; i < 8; i++) {
        const int row = bm * 128 + tm * 8 + i;
        float c0, c1, c2, c3, c4, c5, c6, c7;
        upk2(acc[i][0], c0, c1); upk2(acc[i][1], c2, c3);
        upk2(acc[i][2], c4, c5); upk2(acc[i][3], c6, c7);
        float4* dst = (float4*)&P[row * DM + bn * 128 + tn * 8];
        dst[0] = make_float4(c0, c1, c2, c3);
        dst[1] = make_float4(c4, c5, c6, c7);
    }
}

// ---------------- tropical linear + split-K reduce + activation --------------
// Q/K/V[bh,l,o] = max_i( act[b,l,h*64+i] + Wt[o,i] ),
// act = log1p(relu(sum_z partial)) - lam
__global__ __launch_bounds__(256) void k_trop(const float* __restrict__ Wqt,
                                              const float* __restrict__ Wkt,
                                              const float* __restrict__ Wvt,
                                              const float* __restrict__ lam)
{
    __shared__ float Wts[64][65];   // transposed: Wts[i][o]
    __shared__ float ar[16][65];

    const int gemm = blockIdx.z;
    const float* Wt = (gemm == 0) ? Wqt : ((gemm == 1) ? Wkt : Wvt);
    float* out = (gemm == 0) ? g_Q : ((gemm == 1) ? g_K : g_V);
    const int bh = blockIdx.y;
    const int b = bh >> 3, h = bh & 7;
    const int l0 = blockIdx.x * 16;
    const int tid = threadIdx.x;

    for (int idx = tid; idx < 64 * 64; idx += 256) {
        const int o = idx >> 6, i = idx & 63;
        Wts[i][o] = Wt[idx];
    }
    for (int idx = tid; idx < 16 * 64; idx += 256) {
        const int r = idx >> 6, i = idx & 63;
        const int gidx = (b * LSEQ + l0 + r) * DM + h * DK + i;
        const float* p = g_pp + gemm * 8 * (BL * DM) + gidx;
        float s = 0.0f;
#pragma unroll
        for (int z = 0; z < 8; z++) s += p[z * (BL * DM)];
        ar[r][i] = log1pf(fmaxf(s, 0.0f)) - lam[h * DK + i];
    }
    __syncthreads();

    const int o = tid & 63, rg = tid >> 6;   // rg: 0..3, 4 rows each
    float m[4] = {NEG_BIG, NEG_BIG, NEG_BIG, NEG_BIG};
#pragma unroll 8
    for (int i = 0; i < 64; i++) {
        const float wv = Wts[i][o];
#pragma unroll
        for (int rr = 0; rr < 4; rr++)
            m[rr] = fmaxf(m[rr], ar[rg * 4 + rr][i] + wv);
    }
#pragma unroll
    for (int rr = 0; rr < 4; rr++)
        out[(bh * LSEQ + l0 + rg * 4 + rr) * DK + o] = m[rr];
}

// ---------------- fused tropical attention: scores + context -----------------
// scores[bh,i,j] = min_d(q_i-k_j) - max_d(q_i-k_j)
// ctx[bh,i,d]    = expm1( max_j( scores + v[j,d] ) ), merged to (B,L,DM)
__global__ __launch_bounds__(256, 2) void k_attn(float* __restrict__ scores)
{
    __shared__ float4 Ks[64][16];
    __shared__ float4 Vs[64][16];
    __shared__ float  Ss[64][36];   // transposed scores tile: [j][i]

    const int bh = blockIdx.y;
    const int it = blockIdx.x;        // 0..15
    const int i0 = it * 16;
    const int b = bh >> 3, h = bh & 7;
    const int tid = threadIdx.x;
    const int lane = tid & 31;
    const int w  = tid >> 5;          // warp 0..7 (phase B: i-pair)
    const int ii = tid & 15;          // phase A: i
    const int jg = tid >> 4;          // phase A: j-group 0..15
    const int dg = lane & 7;          // phase B: d-octet
    const int js = lane >> 3;         // phase B: j-split 0..3

    // Q row in registers
    float4 q[16];
    const float4* Qp = (const float4*)(g_Q + (bh * LSEQ + i0 + ii) * DK);
#pragma unroll
    for (int t = 0; t < 16; t++) q[t] = Qp[t];

    float acc[2][8];
#pragma unroll
    for (int i = 0; i < 2; i++)
#pragma unroll
        for (int d = 0; d < 8; d++) acc[i][d] = NEG_BIG;

    for (int c = 0; c < 4; c++) {
        const float4* Kp = (const float4*)(g_K + (bh * LSEQ + c * 64) * DK);
        const float4* Vp = (const float4*)(g_V + (bh * LSEQ + c * 64) * DK);
        for (int idx = tid; idx < 64 * 16; idx += 256) {
            Ks[idx >> 4][idx & 15] = Kp[idx];
            Vs[idx >> 4][idx & 15] = Vp[idx];
        }
        __syncthreads();

        // ---- phase A: scores for this j-chunk ----
#pragma unroll
        for (int jj = 0; jj < 4; jj++) {
            const int j = jg * 4 + jj;
            float mx = NEG_BIG, mn = POS_BIG;
#pragma unroll
            for (int t = 0; t < 16; t++) {
                const float4 kv = Ks[j][t];
                const float d0 = q[t].x - kv.x;
                const float d1 = q[t].y - kv.y;
                const float d2 = q[t].z - kv.z;
                const float d3 = q[t].w - kv.w;
                mx = fmaxf(mx, d0); mn = fminf(mn, d0);
                mx = fmaxf(mx, d1); mn = fminf(mn, d1);
                mx = fmaxf(mx, d2); mn = fminf(mn, d2);
                mx = fmaxf(mx, d3); mn = fminf(mn, d3);
            }
            Ss[j][ii] = mn - mx;
        }
        __syncthreads();

        // coalesced global store of this scores tile
#pragma unroll
        for (int r = 0; r < 4; r++) {
            const int idx = tid + r * 256;
            const int i = idx >> 6, j = idx & 63;
            scores[(bh * LSEQ + i0 + i) * LSEQ + c * 64 + j] = Ss[j][i];
        }

        // ---- phase B: context partial accumulation ----
#pragma unroll 4
        for (int jl = 0; jl < 16; jl++) {
            const int j = js * 16 + jl;
            const float2 s2 = *(const float2*)&Ss[j][w * 2];
            const float4 v0 = Vs[j][dg * 2];
            const float4 v1 = Vs[j][dg * 2 + 1];
            acc[0][0] = fmaxf(acc[0][0], s2.x + v0.x);
            acc[0][1] = fmaxf(acc[0][1], s2.x + v0.y);
            acc[0][2] = fmaxf(acc[0][2], s2.x + v0.z);
            acc[0][3] = fmaxf(acc[0][3], s2.x + v0.w);
            acc[0][4] = fmaxf(acc[0][4], s2.x + v1.x);
            acc[0][5] = fmaxf(acc[0][5], s2.x + v1.y);
            acc[0][6] = fmaxf(acc[0][6], s2.x + v1.z);
            acc[0][7] = fmaxf(acc[0][7], s2.x + v1.w);
            acc[1][0] = fmaxf(acc[1][0], s2.y + v0.x);
            acc[1][1] = fmaxf(acc[1][1], s2.y + v0.y);
            acc[1][2] = fmaxf(acc[1][2], s2.y + v0.z);
            acc[1][3] = fmaxf(acc[1][3], s2.y + v0.w);
            acc[1][4] = fmaxf(acc[1][4], s2.y + v1.x);
            acc[1][5] = fmaxf(acc[1][5], s2.y + v1.y);
            acc[1][6] = fmaxf(acc[1][6], s2.y + v1.z);
            acc[1][7] = fmaxf(acc[1][7], s2.y + v1.w);
        }
        __syncthreads();
    }

    // reduce over the 4 j-splits within each warp
#pragma unroll
    for (int i = 0; i < 2; i++)
#pragma unroll
        for (int d = 0; d < 8; d++) {
            float v = acc[i][d];
            v = fmaxf(v, __shfl_xor_sync(0xffffffffu, v, 8));
            v = fmaxf(v, __shfl_xor_sync(0xffffffffu, v, 16));
            acc[i][d] = v;
        }

    if (js == 0) {
#pragma unroll
        for (int i = 0; i < 2; i++) {
            const int l = i0 + w * 2 + i;
            float4* dst = (float4*)(g_ctx + (b * LSEQ + l) * DM + h * DK + dg * 8);
            dst[0] = make_float4(expm1f(acc[i][0]), expm1f(acc[i][1]),
                                 expm1f(acc[i][2]), expm1f(acc[i][3]));
            dst[1] = make_float4(expm1f(acc[i][4]), expm1f(acc[i][5]),
                                 expm1f(acc[i][6]), expm1f(acc[i][7]));
        }
    }
}

// ---------------- split-K reduce for the output GEMM --------------------------
__global__ __launch_bounds__(256) void k_reduce(float* __restrict__ out)
{
    const int idx = blockIdx.x * 256 + threadIdx.x;   // float4 index, 65536 total
    const float4* p = (const float4*)g_op;
    float4 s = p[idx];
#pragma unroll
    for (int z = 1; z < 8; z++) {
        const float4 t = p[z * 65536 + idx];
        s.x += t.x; s.y += t.y; s.z += t.z; s.w += t.w;
    }
    ((float4*)out)[idx] = s;
}

// ---------------- launch ------------------------------------------------------
extern "C" void kernel_launch(void* const* d_in, const int* in_sizes, int n_in,
                              void* d_out, int out_size)
{
    const float* x   = (const float*)d_in[0];
    const float* Wq  = (const float*)d_in[1];
    const float* Wk  = (const float*)d_in[2];
    const float* Wv  = (const float*)d_in[3];
    const float* Wo  = (const float*)d_in[4];
    const float* lam = (const float*)d_in[5];
    const float* Wqt = (const float*)d_in[6];
    const float* Wkt = (const float*)d_in[7];
    const float* Wvt = (const float*)d_in[8];
    float* out = (float*)d_out;
    float* scores = out + BL * DM;   // (output, attn_scores) flattened in order

    k_gemm<<<dim3(4, 4, 24), 256>>>(x, Wq, Wk, Wv, 0);        // 3 projections, split-K=8
    k_trop<<<dim3(16, 16, 3), 256>>>(Wqt, Wkt, Wvt, lam);     // reduce+activate+tropical
    k_attn<<<dim3(16, 16), 256>>>(scores);                    // fused scores+context
    k_gemm<<<dim3(4, 4, 8), 256>>>(nullptr, Wo, nullptr, nullptr, 1);  // output GEMM
    k_reduce<<<256, 256>>>(out);                              // split-K reduce
}

// round 4
// speedup vs baseline: 1.9289x; 1.0495x over previous
#include <cuda_runtime.h>
#include <math.h>

#define DM   512
#define LSEQ 256
#define BB   2
#define HH   8
#define DK   64
#define BH   16
#define BL   512
#define NEG_BIG -1.0e30f
#define POS_BIG  1.0e30f

typedef unsigned long long ull;

// ---------------- scratch (device globals; no allocations allowed) -----------
__device__ float g_pp[3 * 4 * BL * DM];   // projection split-K partials
__device__ float g_op[8 * BL * DM];       // output GEMM split-K partials
__device__ float g_Q[BH * LSEQ * DK];
__device__ float g_K[BH * LSEQ * DK];
__device__ float g_V[BH * LSEQ * DK];
__device__ float g_ctx[BL * DM];

// ---------------- packed f32x2 helpers (GEMM only) ----------------------------
__device__ __forceinline__ ull pk2(float lo, float hi) {
    ull r;
    asm("mov.b64 %0, {%1, %2};" : "=l"(r) : "f"(lo), "f"(hi));
    return r;
}
__device__ __forceinline__ void upk2(ull v, float& lo, float& hi) {
    asm("mov.b64 {%0, %1}, %2;" : "=f"(lo), "=f"(hi) : "l"(v));
}
__device__ __forceinline__ void fma2(ull& acc, ull a, ull b) {
    asm("fma.rn.f32x2 %0, %1, %2, %0;" : "+l"(acc) : "l"(a), "l"(b));
}

// ---------------- split-K GEMM: 128m x 64n tile, 8x4 per thread, FFMA2 -------
// mode 0: proj (3 gemms, X = x,     P = g_pp, splitK=4, kchunk=128) grid (8,4,12)
// mode 1: out  (1 gemm,  X = g_ctx, P = g_op, splitK=8, kchunk=64)  grid (8,4,8)
__global__ __launch_bounds__(256, 3) void k_gemm(const float* __restrict__ Xin,
                                                 const float* __restrict__ W0,
                                                 const float* __restrict__ W1,
                                                 const float* __restrict__ W2,
                                                 int mode)
{
    __shared__ float As[16][130];   // [kk][i], padded -> conflict-free, aligned ull reads
    __shared__ ull   Bsd[16][65];   // [kk][n] pre-duplicated {b,b}

    int gemm, zk, klen;
    const float* X;
    float* P;
    if (mode == 0) {
        gemm = blockIdx.z >> 2; zk = blockIdx.z & 3; klen = 128;
        X = Xin; P = g_pp + (gemm * 4 + zk) * (BL * DM);
    } else {
        gemm = 0; zk = blockIdx.z; klen = 64;
        X = g_ctx; P = g_op + zk * (BL * DM);
    }
    const float* W = (gemm == 0) ? W0 : ((gemm == 1) ? W1 : W2);

    const int bm = blockIdx.y, bn = blockIdx.x;
    const int tid = threadIdx.x;
    const int tm = tid >> 4;            // 0..15 -> 8 m-rows (as 4 packed pairs)
    const int tn = tid & 15;            // 0..15 -> 4 n-cols (stride 16)
    const int lr = tid >> 2;            // A load row base
    const int lk = (tid & 3) * 4;       // A load k-offset
    const int nr = tid & 63;            // B load row
    const int bq = (tid >> 6) * 4;      // B load k-offset

    ull acc[4][4];
#pragma unroll
    for (int p = 0; p < 4; p++)
#pragma unroll
        for (int j = 0; j < 4; j++) acc[p][j] = 0ULL;

    const int k0 = zk * klen;
    for (int kc = 0; kc < klen; kc += 16) {
#pragma unroll
        for (int pass = 0; pass < 2; pass++) {
            const int r = lr + pass * 64;
            const float4 xa = *(const float4*)&X[(bm * 128 + r) * DM + k0 + kc + lk];
            As[lk + 0][r] = xa.x; As[lk + 1][r] = xa.y;
            As[lk + 2][r] = xa.z; As[lk + 3][r] = xa.w;
        }
        {
            const float4 wb = *(const float4*)&W[(bn * 64 + nr) * DM + k0 + kc + bq];
            Bsd[bq + 0][nr] = pk2(wb.x, wb.x);
            Bsd[bq + 1][nr] = pk2(wb.y, wb.y);
            Bsd[bq + 2][nr] = pk2(wb.z, wb.z);
            Bsd[bq + 3][nr] = pk2(wb.w, wb.w);
        }
        __syncthreads();

#pragma unroll
        for (int kk = 0; kk < 16; kk++) {
            ull a[4], b[4];
#pragma unroll
            for (int p = 0; p < 4; p++) a[p] = *(const ull*)&As[kk][tm * 8 + 2 * p];
#pragma unroll
            for (int j = 0; j < 4; j++) b[j] = Bsd[kk][tn + j * 16];
#pragma unroll
            for (int p = 0; p < 4; p++)
#pragma unroll
                for (int j = 0; j < 4; j++) fma2(acc[p][j], a[p], b[j]);
        }
        __syncthreads();
    }

#pragma unroll
    for (int p = 0; p < 4; p++) {
        const int row = bm * 128 + tm * 8 + 2 * p;
#pragma unroll
        for (int j = 0; j < 4; j++) {
            const int col = bn * 64 + tn + j * 16;
            float lo, hi;
            upk2(acc[p][j], lo, hi);
            P[row * DM + col] = lo;
            P[(row + 1) * DM + col] = hi;
        }
    }
}

// ---------------- tropical linear + split-K reduce + activation ---------------
// Q/K/V[bh,l,o] = max_i( act[b,l,h*64+i] + Wt[o,i] ),
// act = log1p(relu(sum_z partial)) - lam
__global__ __launch_bounds__(256) void k_trop(const float* __restrict__ Wqt,
                                              const float* __restrict__ Wkt,
                                              const float* __restrict__ Wvt,
                                              const float* __restrict__ lam)
{
    __shared__ float Wts[64][65];   // transposed: Wts[i][o] -> broadcast-free reads
    __shared__ float ar[16][65];

    const int gemm = blockIdx.z;
    const float* Wt = (gemm == 0) ? Wqt : ((gemm == 1) ? Wkt : Wvt);
    float* out = (gemm == 0) ? g_Q : ((gemm == 1) ? g_K : g_V);
    const int bh = blockIdx.y;
    const int b = bh >> 3, h = bh & 7;
    const int l0 = blockIdx.x * 16;
    const int tid = threadIdx.x;

    for (int idx = tid; idx < 64 * 64; idx += 256) {
        const int o = idx >> 6, i = idx & 63;
        Wts[i][o] = Wt[idx];
    }
    for (int idx = tid; idx < 16 * 64; idx += 256) {
        const int r = idx >> 6, i = idx & 63;
        const int gidx = (b * LSEQ + l0 + r) * DM + h * DK + i;
        const float* p = g_pp + gemm * 4 * (BL * DM) + gidx;
        float s = p[0] + p[BL * DM] + p[2 * BL * DM] + p[3 * BL * DM];
        ar[r][i] = log1pf(fmaxf(s, 0.0f)) - lam[h * DK + i];
    }
    __syncthreads();

    const int o = tid & 63, rg = tid >> 6;   // 4 rows per thread
    float m[4] = {NEG_BIG, NEG_BIG, NEG_BIG, NEG_BIG};
#pragma unroll 8
    for (int i = 0; i < 64; i++) {
        const float wv = Wts[i][o];
#pragma unroll
        for (int rr = 0; rr < 4; rr++)
            m[rr] = fmaxf(m[rr], ar[rg * 4 + rr][i] + wv);
    }
#pragma unroll
    for (int rr = 0; rr < 4; rr++)
        out[(bh * LSEQ + l0 + rg * 4 + rr) * DK + o] = m[rr];
}

// ---------------- fused tropical attention ------------------------------------
// scores[bh,i,j] = min_d(q_i-k_j) - max_d(q_i-k_j)
// ctx            = expm1( max_j( scores + v[j,d] ) ), merged to (B,L,DM)
__global__ __launch_bounds__(256, 2) void k_attn(float* __restrict__ scores)
{
    __shared__ float4 Ks[64][16];
    __shared__ float  Vs[64][64];
    __shared__ float  Ss[64][34];   // transposed scores tile [j][i]

    const int bh = blockIdx.y;
    const int it = blockIdx.x;
    const int i0 = it * 16;
    const int b = bh >> 3, h = bh & 7;
    const int tid = threadIdx.x;
    const int lane = tid & 31;
    const int w  = tid >> 5;        // warp id: phase B i-pair
    const int ii = tid & 15;        // phase A i
    const int jg = tid >> 4;        // phase A j-group

    // Q row in registers
    float4 q[16];
    const float4* Qp = (const float4*)(g_Q + (bh * LSEQ + i0 + ii) * DK);
#pragma unroll
    for (int t = 0; t < 16; t++) q[t] = Qp[t];

    float a00 = NEG_BIG, a01 = NEG_BIG, a10 = NEG_BIG, a11 = NEG_BIG;

    for (int c = 0; c < 4; c++) {
        const float4* Kp = (const float4*)(g_K + (bh * LSEQ + c * 64) * DK);
        const float4* Vp = (const float4*)(g_V + (bh * LSEQ + c * 64) * DK);
        for (int idx = tid; idx < 1024; idx += 256) {
            const int j = idx >> 4, dq = idx & 15;
            Ks[j][dq] = Kp[idx];
            *(float4*)&Vs[j][dq * 4] = Vp[idx];
        }
        __syncthreads();

        // ---- phase A: scores ----
#pragma unroll
        for (int jj = 0; jj < 4; jj++) {
            const int j = jg * 4 + jj;
            float mx = NEG_BIG, mn = POS_BIG;
#pragma unroll
            for (int t = 0; t < 16; t++) {
                const float4 kv = Ks[j][t];
                const float d0 = q[t].x - kv.x;
                const float d1 = q[t].y - kv.y;
                const float d2 = q[t].z - kv.z;
                const float d3 = q[t].w - kv.w;
                mx = fmaxf(mx, d0); mn = fminf(mn, d0);
                mx = fmaxf(mx, d1); mn = fminf(mn, d1);
                mx = fmaxf(mx, d2); mn = fminf(mn, d2);
                mx = fmaxf(mx, d3); mn = fminf(mn, d3);
            }
            Ss[j][ii] = mn - mx;
        }
        __syncthreads();

        // coalesced global store of scores tile
#pragma unroll
        for (int r = 0; r < 4; r++) {
            const int idx = tid + r * 256;
            const int i = idx >> 6, j = idx & 63;
            scores[(bh * LSEQ + i0 + i) * LSEQ + c * 64 + j] = Ss[j][i];
        }

        // ---- phase B: context (warp = i-pair, d across lanes, j serial) ----
#pragma unroll 4
        for (int j = 0; j < 64; j++) {
            const float2 s2 = *(const float2*)&Ss[j][w * 2];   // warp broadcast
            const float2 v2 = *(const float2*)&Vs[j][lane * 2];
            a00 = fmaxf(a00, s2.x + v2.x);
            a01 = fmaxf(a01, s2.x + v2.y);
            a10 = fmaxf(a10, s2.y + v2.x);
            a11 = fmaxf(a11, s2.y + v2.y);
        }
        __syncthreads();
    }

    // write ctx, merged to (B, L, DM)
    {
        const int l0w = i0 + w * 2;
        float2 v0; v0.x = expm1f(a00); v0.y = expm1f(a01);
        float2 v1; v1.x = expm1f(a10); v1.y = expm1f(a11);
        *(float2*)&g_ctx[(b * LSEQ + l0w) * DM + h * DK + lane * 2] = v0;
        *(float2*)&g_ctx[(b * LSEQ + l0w + 1) * DM + h * DK + lane * 2] = v1;
    }
}

// ---------------- split-K reduce for the output GEMM --------------------------
__global__ __launch_bounds__(256) void k_reduce(float* __restrict__ out)
{
    const int idx = blockIdx.x * 256 + threadIdx.x;   // float4 index, 65536 total
    const float4* p = (const float4*)g_op;
    float4 s = p[idx];
#pragma unroll
    for (int z = 1; z < 8; z++) {
        const float4 t = p[z * 65536 + idx];
        s.x += t.x; s.y += t.y; s.z += t.z; s.w += t.w;
    }
    ((float4*)out)[idx] = s;
}

// ---------------- launch ------------------------------------------------------
extern "C" void kernel_launch(void* const* d_in, const int* in_sizes, int n_in,
                              void* d_out, int out_size)
{
    const float* x   = (const float*)d_in[0];
    const float* Wq  = (const float*)d_in[1];
    const float* Wk  = (const float*)d_in[2];
    const float* Wv  = (const float*)d_in[3];
    const float* Wo  = (const float*)d_in[4];
    const float* lam = (const float*)d_in[5];
    const float* Wqt = (const float*)d_in[6];
    const float* Wkt = (const float*)d_in[7];
    const float* Wvt = (const float*)d_in[8];
    float* out = (float*)d_out;
    float* scores = out + BL * DM;   // (output, attn_scores) flattened in order

    k_gemm<<<dim3(8, 4, 12), 256>>>(x, Wq, Wk, Wv, 0);        // projections, splitK=4
    k_trop<<<dim3(16, 16, 3), 256>>>(Wqt, Wkt, Wvt, lam);     // reduce+activate+tropical
    k_attn<<<dim3(16, 16), 256>>>(scores);                    // fused scores+context
    k_gemm<<<dim3(8, 4, 8), 256>>>(nullptr, Wo, nullptr, nullptr, 1);  // out GEMM, splitK=8
    k_reduce<<<256, 256>>>(out);                              // splitK reduce
}